// round 1
// baseline (speedup 1.0000x reference)
#include <cuda_runtime.h>

#define N_TOTAL 16384
#define BLOCK   256
#define NBLK    (N_TOTAL / BLOCK)   // 64 blocks

// Scratch (no cudaMalloc allowed)
__device__ float        g_exp[N_TOTAL];
__device__ float        g_blocksum[NBLK];
__device__ float        g_sum;     // sum of (pred - log(csum)) over observed
__device__ float        g_cnt;     // n_observed
__device__ unsigned int g_done;    // arrival counter for last-block output write

// ---------------------------------------------------------------------------
// Kernel 1: e = exp(pred), stash e, per-block sum of e. Block 0 resets accums.
// ---------------------------------------------------------------------------
__global__ void nll_k1(const float* __restrict__ pred) {
    const int b = blockIdx.x;
    const int t = threadIdx.x;
    const int i = b * BLOCK + t;

    float e = expf(pred[i]);
    g_exp[i] = e;

    // block reduction of e
    const unsigned lane = t & 31u;
    const unsigned wid  = t >> 5;
    float v = e;
    #pragma unroll
    for (int o = 16; o > 0; o >>= 1)
        v += __shfl_down_sync(0xffffffffu, v, o);

    __shared__ float s_w[BLOCK / 32];
    if (lane == 0) s_w[wid] = v;
    __syncthreads();
    if (t == 0) {
        float tot = 0.f;
        #pragma unroll
        for (int w = 0; w < BLOCK / 32; w++) tot += s_w[w];
        g_blocksum[b] = tot;
        if (b == 0) { g_sum = 0.f; g_cnt = 0.f; g_done = 0u; }
    }
}

// ---------------------------------------------------------------------------
// Kernel 2: block prefix from g_blocksum, in-block inclusive scan of e,
// masked contribution pred - log(csum), global atomic reduce, last block
// writes the outputs.
// ---------------------------------------------------------------------------
__global__ void nll_k2(const float* __restrict__ pred,
                       const float* __restrict__ label,
                       float* __restrict__ out, int out_size) {
    const int b = blockIdx.x;
    const int t = threadIdx.x;
    const int i = b * BLOCK + t;
    const unsigned lane = t & 31u;
    const unsigned wid  = t >> 5;

    __shared__ float s_bs[NBLK];
    __shared__ float s_prefix;
    __shared__ float s_warp[BLOCK / 32];
    __shared__ float s_rs[BLOCK / 32];
    __shared__ float s_rc[BLOCK / 32];

    if (t < NBLK) s_bs[t] = g_blocksum[t];
    __syncthreads();

    if (t == 0) {
        float p = 0.f;
        for (int j = 0; j < b; j++) p += s_bs[j];
        s_prefix = p;
    }

    // in-block inclusive scan of e
    float e = g_exp[i];
    float v = e;
    #pragma unroll
    for (int o = 1; o < 32; o <<= 1) {
        float n = __shfl_up_sync(0xffffffffu, v, o);
        if (lane >= o) v += n;
    }
    if (lane == 31) s_warp[wid] = v;
    __syncthreads();
    if (wid == 0 && lane < (BLOCK / 32)) {
        float w = s_warp[lane];
        #pragma unroll
        for (int o = 1; o < (BLOCK / 32); o <<= 1) {
            float n = __shfl_up_sync(0x000000ffu, w, o);
            if (lane >= (unsigned)o) w += n;
        }
        s_warp[lane] = w;
    }
    __syncthreads();

    float csum = v + (wid ? s_warp[wid - 1] : 0.f) + s_prefix;

    // contribution for observed events
    const float ye = label[2 * i + 1];
    float contrib = 0.f;
    if (ye != 0.f) contrib = ye * (pred[i] - logf(csum));

    // block reduce (contrib, ye)
    float cs = contrib, ys = ye;
    #pragma unroll
    for (int o = 16; o > 0; o >>= 1) {
        cs += __shfl_down_sync(0xffffffffu, cs, o);
        ys += __shfl_down_sync(0xffffffffu, ys, o);
    }
    if (lane == 0) { s_rs[wid] = cs; s_rc[wid] = ys; }
    __syncthreads();

    if (t == 0) {
        float bs = 0.f, bc = 0.f;
        #pragma unroll
        for (int w = 0; w < BLOCK / 32; w++) { bs += s_rs[w]; bc += s_rc[w]; }
        atomicAdd(&g_sum, bs);
        atomicAdd(&g_cnt, bc);
        __threadfence();
        unsigned arrived = atomicAdd(&g_done, 1u);
        if (arrived == NBLK - 1u) {
            float tot_s = atomicAdd(&g_sum, 0.f);   // coherent read
            float tot_c = atomicAdd(&g_cnt, 0.f);
            float cost = (tot_c == 0.f) ? 0.f : -(tot_s / fmaxf(tot_c, 1.f));
            out[0] = cost;
            if (out_size > 1) out[1] = tot_c;
        }
    }
}

extern "C" void kernel_launch(void* const* d_in, const int* in_sizes, int n_in,
                              void* d_out, int out_size) {
    const float* pred  = (const float*)d_in[0];
    const float* label = (const float*)d_in[1];
    float* out = (float*)d_out;

    nll_k1<<<NBLK, BLOCK>>>(pred);
    nll_k2<<<NBLK, BLOCK>>>(pred, label, out, out_size);
}